// round 9
// baseline (speedup 1.0000x reference)
#include <cuda_runtime.h>
#include <cstdint>

// ---------------- problem constants ----------------
#define N_NODES   100000
#define N_EDGES   1600000
#define DHID      128
#define OUTD      64
#define MASK_WORDS 400000         // N_NODES*DHID/32

// ---------------- persistent device scratch (no cudaMalloc allowed) ----------------
__device__ float g_agg[N_NODES * DHID];
__device__ float g_xt1[N_NODES * DHID];
__device__ float g_xs1[N_NODES * DHID];
__device__ float g_xs2[N_NODES * DHID];
__device__ int g_deg_f[N_NODES];
__device__ int g_deg_r[N_NODES];
__device__ int g_rp_f[N_NODES + 1];
__device__ int g_rp_r[N_NODES + 1];
__device__ int g_cur_f[N_NODES];
__device__ int g_cur_r[N_NODES];
__device__ int g_col_f[N_EDGES];
__device__ int g_col_r[N_EDGES];
__device__ int g_bsum_f[128];
__device__ int g_bsum_r[128];
__device__ unsigned g_mask0[MASK_WORDS];
__device__ unsigned g_mask1[MASK_WORDS];
__device__ unsigned g_mask2[MASK_WORDS];

// ---------------- Threefry-2x32 (20 rounds), matches JAX exactly ----------------
__host__ __device__ __forceinline__ void threefry2x32(uint32_t k0, uint32_t k1,
                                                      uint32_t x0, uint32_t x1,
                                                      uint32_t& o0, uint32_t& o1)
{
    uint32_t k2 = k0 ^ k1 ^ 0x1BD11BDAu;
    x0 += k0; x1 += k1;
#define TF_R(r) { x0 += x1; x1 = (x1 << (r)) | (x1 >> (32 - (r))); x1 ^= x0; }
    TF_R(13) TF_R(15) TF_R(26) TF_R(6)  x0 += k1; x1 += k2 + 1u;
    TF_R(17) TF_R(29) TF_R(16) TF_R(24) x0 += k2; x1 += k0 + 2u;
    TF_R(13) TF_R(15) TF_R(26) TF_R(6)  x0 += k0; x1 += k1 + 3u;
    TF_R(17) TF_R(29) TF_R(16) TF_R(24) x0 += k1; x1 += k2 + 4u;
    TF_R(13) TF_R(15) TF_R(26) TF_R(6)  x0 += k2; x1 += k0 + 5u;
#undef TF_R
    o0 = x0; o1 = x1;
}

// ---------------- CSR build ----------------
__global__ void hist_kernel(const int* __restrict__ ed, const int* __restrict__ rd,
                            int* __restrict__ degf, int* __restrict__ degr)
{
    int e = blockIdx.x * 256 + threadIdx.x;          // grid exactly covers N_EDGES
    atomicAdd(&degf[ed[e]], 1);
    atomicAdd(&degr[rd[e]], 1);
}

__global__ void scan_partial(const int* __restrict__ deg, int n,
                             int* __restrict__ out_excl, int* __restrict__ bsum)
{
    __shared__ int sh[1024];
    int i = blockIdx.x * 1024 + threadIdx.x;
    int v = (i < n) ? deg[i] : 0;
    sh[threadIdx.x] = v;
    __syncthreads();
    for (int off = 1; off < 1024; off <<= 1) {
        int t = 0;
        if (threadIdx.x >= off) t = sh[threadIdx.x - off];
        __syncthreads();
        if (threadIdx.x >= off) sh[threadIdx.x] += t;
        __syncthreads();
    }
    if (i < n) out_excl[i] = sh[threadIdx.x] - v;     // exclusive prefix
    if (threadIdx.x == 1023) bsum[blockIdx.x] = sh[1023];
}

__global__ void scan_sums(int* __restrict__ bsum, int nb)
{
    __shared__ int sh[128];
    int v = (threadIdx.x < nb) ? bsum[threadIdx.x] : 0;
    sh[threadIdx.x] = v;
    __syncthreads();
    for (int off = 1; off < 128; off <<= 1) {
        int t = 0;
        if (threadIdx.x >= off) t = sh[threadIdx.x - off];
        __syncthreads();
        if (threadIdx.x >= off) sh[threadIdx.x] += t;
        __syncthreads();
    }
    if (threadIdx.x < nb) bsum[threadIdx.x] = sh[threadIdx.x] - v;  // exclusive
}

__global__ void scan_add(int* __restrict__ rowptr, int* __restrict__ cursor,
                         const int* __restrict__ bsum, int n, int total)
{
    int i = blockIdx.x * 256 + threadIdx.x;
    if (i < n) {
        int r = rowptr[i] + bsum[i >> 10];
        rowptr[i] = r;
        cursor[i] = r;
    }
    if (i == 0) rowptr[n] = total;
}

__global__ void fill_kernel(const int* __restrict__ es, const int* __restrict__ ed,
                            const int* __restrict__ rs, const int* __restrict__ rd,
                            int* __restrict__ curf, int* __restrict__ colf,
                            int* __restrict__ curr, int* __restrict__ colr)
{
    int e = blockIdx.x * 256 + threadIdx.x;
    int p = atomicAdd(&curf[ed[e]], 1); colf[p] = es[e];
    int q = atomicAdd(&curr[rd[e]], 1); colr[q] = rs[e];
}

// ---------------- dropout bitmask: JAX partitionable threefry (default >= 0.4.30), x32 ----
// random_bits(key, 32, shape): per flat element i, 64-bit counter (hi,lo)=(0,i);
// (b1,b2) = threefry2x32(key, (0, i)); bits32 = b1 ^ b2.
// uniform f32: u = bitcast((bits32 >> 9) | 0x3f800000) - 1.0 ; keep = u < 0.9.
__global__ void mask_kernel(unsigned k0, unsigned k1, unsigned* __restrict__ mask)
{
    unsigned i = blockIdx.x * 256u + threadIdx.x;    // grid exactly covers N_NODES*DHID
    uint32_t o0, o1;
    threefry2x32(k0, k1, 0u, i, o0, o1);
    uint32_t bits = o0 ^ o1;
    float u = __uint_as_float((bits >> 9) | 0x3f800000u) - 1.0f;
    unsigned b = __ballot_sync(0xffffffffu, u < 0.9f);
    if ((threadIdx.x & 31u) == 0u) {
        mask[i >> 5] = b;
    }
}

// ---------------- CSR mean-aggregation: one warp per destination node ----------------
__global__ void agg_kernel(const float4* __restrict__ x,
                           const int* __restrict__ rowptr,
                           const int* __restrict__ col,
                           float4* __restrict__ out, int n)
{
    int warp = (blockIdx.x * blockDim.x + threadIdx.x) >> 5;
    int lane = threadIdx.x & 31;
    if (warp >= n) return;
    int s = rowptr[warp], e = rowptr[warp + 1];
    float4 acc = make_float4(0.f, 0.f, 0.f, 0.f);
    for (int base = s; base < e; base += 32) {
        int idx = base + lane;
        int c = (idx < e) ? col[idx] : 0;
        int m = min(32, e - base);
        for (int j = 0; j < m; j++) {
            int cc = __shfl_sync(0xffffffffu, c, j);
            float4 v = x[(size_t)cc * 32 + lane];
            acc.x += v.x; acc.y += v.y; acc.z += v.z; acc.w += v.w;
        }
    }
    float inv = 1.0f / (float)max(e - s, 1);
    acc.x *= inv; acc.y *= inv; acc.z *= inv; acc.w *= inv;
    out[(size_t)warp * 32 + lane] = acc;
}

// ---------------- packed f32x2 helpers ----------------
__device__ __forceinline__ unsigned long long dup_f32(float a)
{
    unsigned long long r;
    asm("mov.b64 %0, {%1, %1};" : "=l"(r) : "r"(__float_as_uint(a)));
    return r;
}
__device__ __forceinline__ unsigned long long pack_f32(float a, float b)
{
    unsigned long long r;
    asm("mov.b64 %0, {%1, %2};" : "=l"(r) : "r"(__float_as_uint(a)), "r"(__float_as_uint(b)));
    return r;
}
__device__ __forceinline__ void ffma2(unsigned long long& c, unsigned long long a,
                                      unsigned long long b)
{
    asm("fma.rn.f32x2 %0, %1, %2, %0;" : "+l"(c) : "l"(a), "l"(b));
}

// ---------------- fused GEMM: C = [A1 | A2] @ [B1 ; B2] + bias, (lrelu+dropout) ----------------
// A* row-major [M,128]; B* row-major [128,BN]; C row-major [M,BN]. A2==null -> K=128.
template <int BN, int TN, bool EPI>
__global__ void __launch_bounds__(256)
gemm_kernel(int M,
            const float* __restrict__ A1, const float* __restrict__ A2,
            const float* __restrict__ B1, const float* __restrict__ B2,
            const float* __restrict__ bias, const unsigned* __restrict__ mask,
            float* __restrict__ C)
{
    constexpr int BM = 128, BK = 8, TM = 8;
    constexpr int NB4 = BK * BN / 4;
    __shared__ float As[2][BK][BM];
    __shared__ float Bs[2][BK][BN];

    const int tid = threadIdx.x;
    const int tx = tid % (BN / TN);
    const int ty = tid / (BN / TN);
    const int rowBase = blockIdx.x * BM;
    const int ar = tid >> 1;
    const int ac = (tid & 1) * 4;
    const int br = (tid < NB4) ? tid / (BN / 4) : 0;
    const int bc = (tid < NB4) ? tid % (BN / 4) : 0;
    const int nk = A2 ? (256 / BK) : (128 / BK);

    unsigned long long acc[TM][TN / 2];
#pragma unroll
    for (int i = 0; i < TM; i++)
#pragma unroll
        for (int j = 0; j < TN / 2; j++) acc[i][j] = 0ull;

    float4 na, nb;
    {   // prologue: tile 0 into stage 0
        int row = rowBase + ar;
        na = (row < M) ? *(const float4*)(A1 + (size_t)row * DHID + ac)
                       : make_float4(0.f, 0.f, 0.f, 0.f);
        if (tid < NB4) nb = *(const float4*)(B1 + br * BN + bc * 4);
        As[0][ac + 0][ar] = na.x; As[0][ac + 1][ar] = na.y;
        As[0][ac + 2][ar] = na.z; As[0][ac + 3][ar] = na.w;
        if (tid < NB4) *(float4*)&Bs[0][br][bc * 4] = nb;
    }
    __syncthreads();

    for (int kt = 0; kt < nk; kt++) {
        const bool has_next = (kt + 1 < nk);
        if (has_next) {
            int kn = (kt + 1) * BK;
            const float* A = (kn < 128) ? A1 : A2;
            const float* B = (kn < 128) ? B1 : B2;
            int k0 = kn & 127;
            int row = rowBase + ar;
            na = (row < M) ? *(const float4*)(A + (size_t)row * DHID + k0 + ac)
                           : make_float4(0.f, 0.f, 0.f, 0.f);
            if (tid < NB4) nb = *(const float4*)(B + (k0 + br) * BN + bc * 4);
        }
        const int s = kt & 1;
#pragma unroll
        for (int kk = 0; kk < BK; kk++) {
            float a[TM];
            *(float4*)&a[0] = *(const float4*)&As[s][kk][ty * TM];
            *(float4*)&a[4] = *(const float4*)&As[s][kk][ty * TM + 4];
            unsigned long long bp[4];
            float4 b0 = *(const float4*)&Bs[s][kk][tx * TN];
            bp[0] = pack_f32(b0.x, b0.y);
            bp[1] = pack_f32(b0.z, b0.w);
            if (TN == 8) {
                float4 b1 = *(const float4*)&Bs[s][kk][tx * TN + 4];
                bp[2] = pack_f32(b1.x, b1.y);
                bp[3] = pack_f32(b1.z, b1.w);
            }
#pragma unroll
            for (int i = 0; i < TM; i++) {
                unsigned long long a2 = dup_f32(a[i]);
#pragma unroll
                for (int j = 0; j < TN / 2; j++) ffma2(acc[i][j], a2, bp[j]);
            }
        }
        if (has_next) {
            const int s2 = (kt + 1) & 1;
            As[s2][ac + 0][ar] = na.x; As[s2][ac + 1][ar] = na.y;
            As[s2][ac + 2][ar] = na.z; As[s2][ac + 3][ar] = na.w;
            if (tid < NB4) *(float4*)&Bs[s2][br][bc * 4] = nb;
            __syncthreads();
        }
    }

    // epilogue: bias (+ leaky_relu + exact-JAX dropout)
#pragma unroll
    for (int i = 0; i < TM; i++) {
        int row = rowBase + ty * TM + i;
        if (row < M) {
            float v[TN];
#pragma unroll
            for (int j = 0; j < TN / 2; j++) {
                v[2 * j]     = __uint_as_float((unsigned)(acc[i][j] & 0xffffffffull));
                v[2 * j + 1] = __uint_as_float((unsigned)(acc[i][j] >> 32));
            }
            const int j0 = tx * TN;
            unsigned mbits = 0;
            if (EPI) {
                unsigned flat = (unsigned)row * 128u + (unsigned)j0;
                mbits = mask[flat >> 5] >> (flat & 31u);
            }
#pragma unroll
            for (int jj = 0; jj < TN; jj++) {
                float o = v[jj] + bias[j0 + jj];
                if (EPI) {
                    o = (o >= 0.0f) ? o : 0.01f * o;
                    o = ((mbits >> jj) & 1u) ? o * (1.0f / 0.9f) : 0.0f;
                }
                C[(size_t)row * BN + j0 + jj] = o;
            }
        }
    }
}

// ---------------- host orchestration ----------------
extern "C" void kernel_launch(void* const* d_in, const int* in_sizes, int n_in,
                              void* d_out, int out_size)
{
    const float* x_src  = (const float*)d_in[0];
    const float* x_tgt  = (const float*)d_in[1];
    const float* Wl_tgt = (const float*)d_in[2];
    const float* bl_tgt = (const float*)d_in[3];
    const float* Wr_tgt = (const float*)d_in[4];
    const float* Wl_src = (const float*)d_in[5];
    const float* bl_src = (const float*)d_in[6];
    const float* Wr_src = (const float*)d_in[7];
    const float* W_out  = (const float*)d_in[8];
    const float* b_out  = (const float*)d_in[9];
    const int* edge_src = (const int*)d_in[10];
    const int* edge_dst = (const int*)d_in[11];
    const int* rev_src  = (const int*)d_in[12];
    const int* rev_dst  = (const int*)d_in[13];
    float* out = (float*)d_out;

    float *agg, *xt1, *xs1, *xs2;
    int *degf, *degr, *rpf, *rpr, *curf, *curr, *colf, *colr, *bsf, *bsr;
    unsigned *m0, *m1, *m2;
    cudaGetSymbolAddress((void**)&agg,  g_agg);
    cudaGetSymbolAddress((void**)&xt1,  g_xt1);
    cudaGetSymbolAddress((void**)&xs1,  g_xs1);
    cudaGetSymbolAddress((void**)&xs2,  g_xs2);
    cudaGetSymbolAddress((void**)&degf, g_deg_f);
    cudaGetSymbolAddress((void**)&degr, g_deg_r);
    cudaGetSymbolAddress((void**)&rpf,  g_rp_f);
    cudaGetSymbolAddress((void**)&rpr,  g_rp_r);
    cudaGetSymbolAddress((void**)&curf, g_cur_f);
    cudaGetSymbolAddress((void**)&curr, g_cur_r);
    cudaGetSymbolAddress((void**)&colf, g_col_f);
    cudaGetSymbolAddress((void**)&colr, g_col_r);
    cudaGetSymbolAddress((void**)&bsf,  g_bsum_f);
    cudaGetSymbolAddress((void**)&bsr,  g_bsum_r);
    cudaGetSymbolAddress((void**)&m0,   g_mask0);
    cudaGetSymbolAddress((void**)&m1,   g_mask1);
    cudaGetSymbolAddress((void**)&m2,   g_mask2);

    // JAX dropout keys: fold_in(key(42), d) = threefry((0,42), (0,d)) — unchanged by
    // the partitionable flag (fold_in still uses the split-halves threefry_2x32).
    uint32_t k0a, k1a, k0b, k1b, k0c, k1c;
    threefry2x32(0u, 42u, 0u, 0u, k0a, k1a);  // layer0 target  (fold 0)
    threefry2x32(0u, 42u, 0u, 1u, k0b, k1b);  // layer0 source  (fold 1)
    threefry2x32(0u, 42u, 0u, 3u, k0c, k1c);  // layer1 source  (fold 3)

    const int NB_SCAN = (N_NODES + 1023) / 1024;          // 98
    const int EB = N_EDGES / 256;                          // 6250 exact
    const int MB = (N_NODES * DHID) / 256;                 // 50000 exact
    const int AGGB = N_NODES / 8;                          // 12500 (8 warps/block)
    const int GB = (N_NODES + 127) / 128;                  // 782

    // --- CSR build (fwd: edge_dst<-edge_src ; rev: rev_dst<-rev_src) ---
    cudaMemsetAsync(degf, 0, N_NODES * sizeof(int));
    cudaMemsetAsync(degr, 0, N_NODES * sizeof(int));
    hist_kernel<<<EB, 256>>>(edge_dst, rev_dst, degf, degr);
    scan_partial<<<NB_SCAN, 1024>>>(degf, N_NODES, rpf, bsf);
    scan_partial<<<NB_SCAN, 1024>>>(degr, N_NODES, rpr, bsr);
    scan_sums<<<1, 128>>>(bsf, NB_SCAN);
    scan_sums<<<1, 128>>>(bsr, NB_SCAN);
    scan_add<<<(N_NODES + 255) / 256, 256>>>(rpf, curf, bsf, N_NODES, N_EDGES);
    scan_add<<<(N_NODES + 255) / 256, 256>>>(rpr, curr, bsr, N_NODES, N_EDGES);
    fill_kernel<<<EB, 256>>>(edge_src, edge_dst, rev_src, rev_dst, curf, colf, curr, colr);

    // --- dropout bitmasks (partitionable-threefry, x32 float path) ---
    mask_kernel<<<MB, 256>>>(k0a, k1a, m0);
    mask_kernel<<<MB, 256>>>(k0b, k1b, m1);
    mask_kernel<<<MB, 256>>>(k0c, k1c, m2);

    // --- layer 0, target conv: mean over fwd edges of x_source ---
    agg_kernel<<<AGGB, 256>>>((const float4*)x_src, rpf, colf, (float4*)agg, N_NODES);
    gemm_kernel<128, 8, true><<<GB, 256>>>(N_NODES, agg, x_tgt,
                                           Wl_tgt, Wr_tgt, bl_tgt, m0, xt1);

    // --- layer 0, source conv: mean over rev edges of x_target ---
    agg_kernel<<<AGGB, 256>>>((const float4*)x_tgt, rpr, colr, (float4*)agg, N_NODES);
    gemm_kernel<128, 8, true><<<GB, 256>>>(N_NODES, agg, x_src,
                                           Wl_src, Wr_src, bl_src, m1, xs1);

    // --- layer 1, source conv only (layer-1 target embedding is dead code) ---
    agg_kernel<<<AGGB, 256>>>((const float4*)xt1, rpr, colr, (float4*)agg, N_NODES);
    gemm_kernel<128, 8, true><<<GB, 256>>>(N_NODES, agg, xs1,
                                           Wl_src + DHID * DHID, Wr_src + DHID * DHID,
                                           bl_src + DHID, m2, xs2);

    // --- output projection ---
    gemm_kernel<64, 4, false><<<GB, 256>>>(N_NODES, xs2, nullptr,
                                           W_out, nullptr, b_out, nullptr, out);
}

// round 10
// speedup vs baseline: 1.0679x; 1.0679x over previous
#include <cuda_runtime.h>
#include <cstdint>

// ---------------- problem constants ----------------
#define N_NODES   100000
#define N_EDGES   1600000
#define DHID      128
#define OUTD      64
#define NB_SCAN   98              // ceil(N_NODES/1024)
#define FLAG_AGG  (1ull << 62)
#define FLAG_PRE  (1ull << 63)

// ---------------- persistent device scratch (no cudaMalloc allowed) ----------------
__device__ float g_agg[N_NODES * DHID];
__device__ float g_xt1[N_NODES * DHID];
__device__ float g_xs1[N_NODES * DHID];
__device__ float g_xs2[N_NODES * DHID];
__device__ int g_deg[2 * N_NODES];            // [0]=fwd, [1]=rev — one memset covers both
__device__ int g_rp[2 * (N_NODES + 1)];
__device__ int g_cur[2 * N_NODES];
__device__ int g_col[2 * N_EDGES];
__device__ unsigned long long g_status[2 * NB_SCAN];

// ---------------- Threefry-2x32 (20 rounds), matches JAX exactly ----------------
__host__ __device__ __forceinline__ void threefry2x32(uint32_t k0, uint32_t k1,
                                                      uint32_t x0, uint32_t x1,
                                                      uint32_t& o0, uint32_t& o1)
{
    uint32_t k2 = k0 ^ k1 ^ 0x1BD11BDAu;
    x0 += k0; x1 += k1;
#define TF_R(r) { x0 += x1; x1 = (x1 << (r)) | (x1 >> (32 - (r))); x1 ^= x0; }
    TF_R(13) TF_R(15) TF_R(26) TF_R(6)  x0 += k1; x1 += k2 + 1u;
    TF_R(17) TF_R(29) TF_R(16) TF_R(24) x0 += k2; x1 += k0 + 2u;
    TF_R(13) TF_R(15) TF_R(26) TF_R(6)  x0 += k0; x1 += k1 + 3u;
    TF_R(17) TF_R(29) TF_R(16) TF_R(24) x0 += k1; x1 += k2 + 4u;
    TF_R(13) TF_R(15) TF_R(26) TF_R(6)  x0 += k2; x1 += k0 + 5u;
#undef TF_R
    o0 = x0; o1 = x1;
}

// partitionable-threefry keep bit for flat element index (x32 float path)
__device__ __forceinline__ bool drop_keep(uint32_t k0, uint32_t k1, uint32_t flat)
{
    uint32_t o0, o1;
    threefry2x32(k0, k1, 0u, flat, o0, o1);
    uint32_t bits = o0 ^ o1;
    float u = __uint_as_float((bits >> 9) | 0x3f800000u) - 1.0f;
    return u < 0.9f;
}

// ---------------- CSR build: histogram (also resets lookback status) ----------------
__global__ void hist_kernel(const int* __restrict__ ed, const int* __restrict__ rd,
                            int* __restrict__ degf, int* __restrict__ degr,
                            unsigned long long* __restrict__ status)
{
    int e = blockIdx.x * 256 + threadIdx.x;          // grid exactly covers N_EDGES
    if (e < 2 * NB_SCAN) status[e] = 0ull;           // reset for next launch (kernel-boundary ordered)
    atomicAdd(&degf[ed[e]], 1);
    atomicAdd(&degr[rd[e]], 1);
}

// ---------------- single-pass exclusive scan: decoupled lookback, both graphs ----------------
__global__ void __launch_bounds__(1024)
scan_csr(const int* __restrict__ deg, int* __restrict__ rowptr,
         int* __restrict__ cursor, unsigned long long* __restrict__ status)
{
    __shared__ int sh[1024];
    __shared__ int s_excl;
    const int g = blockIdx.y;
    const int b = blockIdx.x;
    const int tid = threadIdx.x;
    const int i = b * 1024 + tid;
    const int* dg = deg + g * N_NODES;
    int* rp = rowptr + g * (N_NODES + 1);
    int* cur = cursor + g * N_NODES;
    unsigned long long* st = status + g * NB_SCAN;

    int v = (i < N_NODES) ? dg[i] : 0;
    sh[tid] = v;
    __syncthreads();
    for (int off = 1; off < 1024; off <<= 1) {
        int t = 0;
        if (tid >= off) t = sh[tid - off];
        __syncthreads();
        if (tid >= off) sh[tid] += t;
        __syncthreads();
    }
    const int bsum = sh[1023];

    if (tid == 0) {
        unsigned long long val = (unsigned long long)(unsigned)bsum;
        if (b == 0) {
            atomicExch(&st[0], FLAG_PRE | val);
            s_excl = 0;
            rp[N_NODES] = N_EDGES;
        } else {
            atomicExch(&st[b], FLAG_AGG | val);
        }
    }
    // warp-windowed lookback (warp 0). All 196 blocks co-resident -> no deadlock.
    if (b > 0 && tid < 32) {
        const int lane = tid;
        long long excl = 0;
        int idx = b - 1;
        bool done = false;
        while (!done) {
            int p = idx - lane;
            unsigned long long s = 0;
            if (p >= 0) {
                do { s = atomicAdd(&st[p], 0ull); } while (!(s & (FLAG_AGG | FLAG_PRE)));
            }
            unsigned pre = __ballot_sync(0xffffffffu, (p >= 0) && (s & FLAG_PRE));
            bool inc;
            if (pre) { int k = __ffs(pre) - 1; inc = (p >= 0) && (lane <= k); done = true; }
            else     { inc = (p >= 0); if (idx < 32) done = true; /* guard; block0=PRE */ }
            long long val = inc ? (long long)(s & 0xffffffffull) : 0;
#pragma unroll
            for (int o = 16; o > 0; o >>= 1) val += __shfl_down_sync(0xffffffffu, val, o);
            if (lane == 0) excl += val;
            idx -= 32;
        }
        if (lane == 0) {
            s_excl = (int)excl;
            atomicExch(&st[b], FLAG_PRE | (unsigned long long)(unsigned)(excl + bsum));
        }
    }
    __syncthreads();
    int e = s_excl + sh[tid] - v;                    // exclusive prefix
    if (i < N_NODES) { rp[i] = e; cur[i] = e; }
}

__global__ void fill_kernel(const int* __restrict__ es, const int* __restrict__ ed,
                            const int* __restrict__ rs, const int* __restrict__ rd,
                            int* __restrict__ curf, int* __restrict__ colf,
                            int* __restrict__ curr, int* __restrict__ colr)
{
    int e = blockIdx.x * 256 + threadIdx.x;
    int p = atomicAdd(&curf[ed[e]], 1); colf[p] = es[e];
    int q = atomicAdd(&curr[rd[e]], 1); colr[q] = rs[e];
}

// ---------------- CSR mean-aggregation: one warp per destination node ----------------
__global__ void agg_kernel(const float4* __restrict__ x,
                           const int* __restrict__ rowptr,
                           const int* __restrict__ col,
                           float4* __restrict__ out, int n)
{
    int warp = (blockIdx.x * blockDim.x + threadIdx.x) >> 5;
    int lane = threadIdx.x & 31;
    if (warp >= n) return;
    int s = rowptr[warp], e = rowptr[warp + 1];
    float4 acc = make_float4(0.f, 0.f, 0.f, 0.f);
    for (int base = s; base < e; base += 32) {
        int idx = base + lane;
        int c = (idx < e) ? col[idx] : 0;
        int m = min(32, e - base);
        for (int j = 0; j < m; j++) {
            int cc = __shfl_sync(0xffffffffu, c, j);
            float4 v = x[(size_t)cc * 32 + lane];
            acc.x += v.x; acc.y += v.y; acc.z += v.z; acc.w += v.w;
        }
    }
    float inv = 1.0f / (float)max(e - s, 1);
    acc.x *= inv; acc.y *= inv; acc.z *= inv; acc.w *= inv;
    out[(size_t)warp * 32 + lane] = acc;
}

// ---------------- packed f32x2 helpers ----------------
__device__ __forceinline__ unsigned long long dup_f32(float a)
{
    unsigned long long r;
    asm("mov.b64 %0, {%1, %1};" : "=l"(r) : "r"(__float_as_uint(a)));
    return r;
}
__device__ __forceinline__ unsigned long long pack_f32(float a, float b)
{
    unsigned long long r;
    asm("mov.b64 %0, {%1, %2};" : "=l"(r) : "r"(__float_as_uint(a)), "r"(__float_as_uint(b)));
    return r;
}
__device__ __forceinline__ void ffma2(unsigned long long& c, unsigned long long a,
                                      unsigned long long b)
{
    asm("fma.rn.f32x2 %0, %1, %2, %0;" : "+l"(c) : "l"(a), "l"(b));
}

// ---------------- fused GEMM: C = [A1 | A2] @ [B1 ; B2] + bias, (lrelu + fused dropout) ----
// A* row-major [M,128]; B* row-major [128,BN]; C row-major [M,BN]. A2==null -> K=128.
// EPI path computes the JAX partitionable-threefry keep bit inline per output element.
template <int BN, int TN, bool EPI>
__global__ void __launch_bounds__(256)
gemm_kernel(int M,
            const float* __restrict__ A1, const float* __restrict__ A2,
            const float* __restrict__ B1, const float* __restrict__ B2,
            const float* __restrict__ bias,
            uint32_t mk0, uint32_t mk1,
            float* __restrict__ C)
{
    constexpr int BM = 128, BK = 8, TM = 8;
    constexpr int NB4 = BK * BN / 4;
    __shared__ float As[2][BK][BM];
    __shared__ float Bs[2][BK][BN];

    const int tid = threadIdx.x;
    const int tx = tid % (BN / TN);
    const int ty = tid / (BN / TN);
    const int rowBase = blockIdx.x * BM;
    const int ar = tid >> 1;
    const int ac = (tid & 1) * 4;
    const int br = (tid < NB4) ? tid / (BN / 4) : 0;
    const int bc = (tid < NB4) ? tid % (BN / 4) : 0;
    const int nk = A2 ? (256 / BK) : (128 / BK);

    unsigned long long acc[TM][TN / 2];
#pragma unroll
    for (int i = 0; i < TM; i++)
#pragma unroll
        for (int j = 0; j < TN / 2; j++) acc[i][j] = 0ull;

    float4 na, nb;
    {   // prologue: tile 0 into stage 0
        int row = rowBase + ar;
        na = (row < M) ? *(const float4*)(A1 + (size_t)row * DHID + ac)
                       : make_float4(0.f, 0.f, 0.f, 0.f);
        if (tid < NB4) nb = *(const float4*)(B1 + br * BN + bc * 4);
        As[0][ac + 0][ar] = na.x; As[0][ac + 1][ar] = na.y;
        As[0][ac + 2][ar] = na.z; As[0][ac + 3][ar] = na.w;
        if (tid < NB4) *(float4*)&Bs[0][br][bc * 4] = nb;
    }
    __syncthreads();

    for (int kt = 0; kt < nk; kt++) {
        const bool has_next = (kt + 1 < nk);
        if (has_next) {
            int kn = (kt + 1) * BK;
            const float* A = (kn < 128) ? A1 : A2;
            const float* B = (kn < 128) ? B1 : B2;
            int k0 = kn & 127;
            int row = rowBase + ar;
            na = (row < M) ? *(const float4*)(A + (size_t)row * DHID + k0 + ac)
                           : make_float4(0.f, 0.f, 0.f, 0.f);
            if (tid < NB4) nb = *(const float4*)(B + (k0 + br) * BN + bc * 4);
        }
        const int s = kt & 1;
#pragma unroll
        for (int kk = 0; kk < BK; kk++) {
            float a[TM];
            *(float4*)&a[0] = *(const float4*)&As[s][kk][ty * TM];
            *(float4*)&a[4] = *(const float4*)&As[s][kk][ty * TM + 4];
            unsigned long long bp[4];
            float4 b0 = *(const float4*)&Bs[s][kk][tx * TN];
            bp[0] = pack_f32(b0.x, b0.y);
            bp[1] = pack_f32(b0.z, b0.w);
            if (TN == 8) {
                float4 b1 = *(const float4*)&Bs[s][kk][tx * TN + 4];
                bp[2] = pack_f32(b1.x, b1.y);
                bp[3] = pack_f32(b1.z, b1.w);
            }
#pragma unroll
            for (int i = 0; i < TM; i++) {
                unsigned long long a2 = dup_f32(a[i]);
#pragma unroll
                for (int j = 0; j < TN / 2; j++) ffma2(acc[i][j], a2, bp[j]);
            }
        }
        if (has_next) {
            const int s2 = (kt + 1) & 1;
            As[s2][ac + 0][ar] = na.x; As[s2][ac + 1][ar] = na.y;
            As[s2][ac + 2][ar] = na.z; As[s2][ac + 3][ar] = na.w;
            if (tid < NB4) *(float4*)&Bs[s2][br][bc * 4] = nb;
            __syncthreads();
        }
    }

    // epilogue: bias (+ leaky_relu + inline exact-JAX dropout)
#pragma unroll
    for (int i = 0; i < TM; i++) {
        int row = rowBase + ty * TM + i;
        if (row < M) {
            float v[TN];
#pragma unroll
            for (int j = 0; j < TN / 2; j++) {
                v[2 * j]     = __uint_as_float((unsigned)(acc[i][j] & 0xffffffffull));
                v[2 * j + 1] = __uint_as_float((unsigned)(acc[i][j] >> 32));
            }
            const int j0 = tx * TN;
#pragma unroll
            for (int jj = 0; jj < TN; jj++) {
                float o = v[jj] + bias[j0 + jj];
                if (EPI) {
                    o = (o >= 0.0f) ? o : 0.01f * o;
                    uint32_t flat = (uint32_t)row * 128u + (uint32_t)(j0 + jj);
                    o = drop_keep(mk0, mk1, flat) ? o * (1.0f / 0.9f) : 0.0f;
                }
                C[(size_t)row * BN + j0 + jj] = o;
            }
        }
    }
}

// ---------------- host orchestration ----------------
extern "C" void kernel_launch(void* const* d_in, const int* in_sizes, int n_in,
                              void* d_out, int out_size)
{
    const float* x_src  = (const float*)d_in[0];
    const float* x_tgt  = (const float*)d_in[1];
    const float* Wl_tgt = (const float*)d_in[2];
    const float* bl_tgt = (const float*)d_in[3];
    const float* Wr_tgt = (const float*)d_in[4];
    const float* Wl_src = (const float*)d_in[5];
    const float* bl_src = (const float*)d_in[6];
    const float* Wr_src = (const float*)d_in[7];
    const float* W_out  = (const float*)d_in[8];
    const float* b_out  = (const float*)d_in[9];
    const int* edge_src = (const int*)d_in[10];
    const int* edge_dst = (const int*)d_in[11];
    const int* rev_src  = (const int*)d_in[12];
    const int* rev_dst  = (const int*)d_in[13];
    float* out = (float*)d_out;

    float *agg, *xt1, *xs1, *xs2;
    int *deg, *rp, *cur, *col;
    unsigned long long* status;
    cudaGetSymbolAddress((void**)&agg,    g_agg);
    cudaGetSymbolAddress((void**)&xt1,    g_xt1);
    cudaGetSymbolAddress((void**)&xs1,    g_xs1);
    cudaGetSymbolAddress((void**)&xs2,    g_xs2);
    cudaGetSymbolAddress((void**)&deg,    g_deg);
    cudaGetSymbolAddress((void**)&rp,     g_rp);
    cudaGetSymbolAddress((void**)&cur,    g_cur);
    cudaGetSymbolAddress((void**)&col,    g_col);
    cudaGetSymbolAddress((void**)&status, g_status);

    int* degf = deg;
    int* degr = deg + N_NODES;
    int* rpf  = rp;
    int* rpr  = rp + (N_NODES + 1);
    int* curf = cur;
    int* curr = cur + N_NODES;
    int* colf = col;
    int* colr = col + N_EDGES;

    // JAX dropout keys: fold_in(key(42), d) = threefry((0,42), (0,d))
    uint32_t k0a, k1a, k0b, k1b, k0c, k1c;
    threefry2x32(0u, 42u, 0u, 0u, k0a, k1a);  // layer0 target  (fold 0)
    threefry2x32(0u, 42u, 0u, 1u, k0b, k1b);  // layer0 source  (fold 1)
    threefry2x32(0u, 42u, 0u, 3u, k0c, k1c);  // layer1 source  (fold 3)

    const int EB = N_EDGES / 256;                          // 6250 exact
    const int AGGB = N_NODES / 8;                          // 12500 (8 warps/block)
    const int GB = (N_NODES + 127) / 128;                  // 782

    // launch index:                                     0: memset
    cudaMemsetAsync(deg, 0, 2 * N_NODES * sizeof(int));
    //                                                   1: hist (+status reset)
    hist_kernel<<<EB, 256>>>(edge_dst, rev_dst, degf, degr, status);
    //                                                   2: single-pass scan, both graphs
    scan_csr<<<dim3(NB_SCAN, 2), 1024>>>(deg, rp, cur, status);
    //                                                   3: fill
    fill_kernel<<<EB, 256>>>(edge_src, edge_dst, rev_src, rev_dst, curf, colf, curr, colr);

    //                                                   4: agg   5: gemm  <-- ncu -s 5 target
    agg_kernel<<<AGGB, 256>>>((const float4*)x_src, rpf, colf, (float4*)agg, N_NODES);
    gemm_kernel<128, 8, true><<<GB, 256>>>(N_NODES, agg, x_tgt,
                                           Wl_tgt, Wr_tgt, bl_tgt, k0a, k1a, xt1);

    agg_kernel<<<AGGB, 256>>>((const float4*)x_tgt, rpr, colr, (float4*)agg, N_NODES);
    gemm_kernel<128, 8, true><<<GB, 256>>>(N_NODES, agg, x_src,
                                           Wl_src, Wr_src, bl_src, k0b, k1b, xs1);

    // layer 1, source conv only (layer-1 target embedding is dead code)
    agg_kernel<<<AGGB, 256>>>((const float4*)xt1, rpr, colr, (float4*)agg, N_NODES);
    gemm_kernel<128, 8, true><<<GB, 256>>>(N_NODES, agg, xs1,
                                           Wl_src + DHID * DHID, Wr_src + DHID * DHID,
                                           bl_src + DHID, k0c, k1c, xs2);

    gemm_kernel<64, 4, false><<<GB, 256>>>(N_NODES, xs2, nullptr,
                                           W_out, nullptr, b_out, 0u, 0u, out);
}

// round 12
// speedup vs baseline: 1.3136x; 1.2300x over previous
#include <cuda_runtime.h>
#include <cuda_bf16.h>
#include <cstdint>

// ---------------- problem constants ----------------
#define N_NODES   100000
#define N_EDGES   1600000
#define DHID      128
#define OUTD      64
#define NB_SCAN   98              // ceil(N_NODES/1024)
#define FLAG_AGG  (1ull << 62)
#define FLAG_PRE  (1ull << 63)

// ---------------- persistent device scratch (no cudaMalloc allowed) ----------------
__device__ float g_agg[N_NODES * DHID];
__device__ float g_xt1[N_NODES * DHID];
__device__ float g_xs1[N_NODES * DHID];
__device__ float g_xs2[N_NODES * DHID];
__device__ int g_deg[2 * N_NODES];
__device__ int g_rp[2 * (N_NODES + 1)];
__device__ int g_cur[2 * N_NODES];
__device__ int g_col[2 * N_EDGES];
__device__ unsigned long long g_status[2 * NB_SCAN];
// pre-transposed + bf16-split weights: [conv][n=128][k=256] and out [n=64][k=128]
__device__ __nv_bfloat16 g_Bhi[3 * 128 * 256];
__device__ __nv_bfloat16 g_Blo[3 * 128 * 256];
__device__ __nv_bfloat16 g_Bohi[64 * 128];
__device__ __nv_bfloat16 g_Bolo[64 * 128];

// ---------------- Threefry-2x32 (20 rounds), matches JAX exactly ----------------
__host__ __device__ __forceinline__ void threefry2x32(uint32_t k0, uint32_t k1,
                                                      uint32_t x0, uint32_t x1,
                                                      uint32_t& o0, uint32_t& o1)
{
    uint32_t k2 = k0 ^ k1 ^ 0x1BD11BDAu;
    x0 += k0; x1 += k1;
#define TF_R(r) { x0 += x1; x1 = (x1 << (r)) | (x1 >> (32 - (r))); x1 ^= x0; }
    TF_R(13) TF_R(15) TF_R(26) TF_R(6)  x0 += k1; x1 += k2 + 1u;
    TF_R(17) TF_R(29) TF_R(16) TF_R(24) x0 += k2; x1 += k0 + 2u;
    TF_R(13) TF_R(15) TF_R(26) TF_R(6)  x0 += k0; x1 += k1 + 3u;
    TF_R(17) TF_R(29) TF_R(16) TF_R(24) x0 += k1; x1 += k2 + 4u;
    TF_R(13) TF_R(15) TF_R(26) TF_R(6)  x0 += k2; x1 += k0 + 5u;
#undef TF_R
    o0 = x0; o1 = x1;
}

// partitionable-threefry keep bit (x32 float path) — verified exact vs reference
__device__ __forceinline__ bool drop_keep(uint32_t k0, uint32_t k1, uint32_t flat)
{
    uint32_t o0, o1;
    threefry2x32(k0, k1, 0u, flat, o0, o1);
    uint32_t bits = o0 ^ o1;
    float u = __uint_as_float((bits >> 9) | 0x3f800000u) - 1.0f;
    return u < 0.9f;
}

// ---------------- small helpers ----------------
__device__ __forceinline__ uint32_t smem_u32(const void* p)
{
    uint32_t a;
    asm("{ .reg .u64 t; cvta.to.shared.u64 t, %1; cvt.u32.u64 %0, t; }" : "=r"(a) : "l"(p));
    return a;
}
__device__ __forceinline__ void cp8(uint32_t dst, const void* src)
{
    asm volatile("cp.async.ca.shared.global [%0], [%1], 8;" :: "r"(dst), "l"(src));
}
#define CP_COMMIT() asm volatile("cp.async.commit_group;" ::: "memory")
#define CP_WAIT0()  asm volatile("cp.async.wait_group 0;" ::: "memory")

__device__ __forceinline__ uint32_t bfp(__nv_bfloat16 a, __nv_bfloat16 b)
{
    uint16_t ra = *reinterpret_cast<uint16_t*>(&a);
    uint16_t rb = *reinterpret_cast<uint16_t*>(&b);
    return (uint32_t)ra | ((uint32_t)rb << 16);
}
__device__ __forceinline__ void mma_bf16(float* c,
                                         uint32_t a0, uint32_t a1, uint32_t a2, uint32_t a3,
                                         uint32_t b0, uint32_t b1)
{
    asm volatile("mma.sync.aligned.m16n8k16.row.col.f32.bf16.bf16.f32 "
                 "{%0,%1,%2,%3}, {%4,%5,%6,%7}, {%8,%9}, {%0,%1,%2,%3};"
                 : "+f"(c[0]), "+f"(c[1]), "+f"(c[2]), "+f"(c[3])
                 : "r"(a0), "r"(a1), "r"(a2), "r"(a3), "r"(b0), "r"(b1));
}

// ---------------- weight prep: transpose to [N][K] + bf16 hi/lo split ----------------
__global__ void prep_w(const float* __restrict__ Wl_tgt, const float* __restrict__ Wr_tgt,
                       const float* __restrict__ Wl_src, const float* __restrict__ Wr_src,
                       const float* __restrict__ W_out)
{
    int idx = blockIdx.x * 256 + threadIdx.x;       // grid exactly covers 106496
    float v;
    if (idx < 3 * 128 * 256) {
        int c = idx >> 15;
        int rem = idx & 32767;
        int n = rem >> 8;
        int k = rem & 255;
        const float* Wl = (c == 0) ? Wl_tgt : (c == 1 ? Wl_src : Wl_src + 16384);
        const float* Wr = (c == 0) ? Wr_tgt : (c == 1 ? Wr_src : Wr_src + 16384);
        v = (k < 128) ? Wl[k * 128 + n] : Wr[(k - 128) * 128 + n];
        __nv_bfloat16 h = __float2bfloat16_rn(v);
        g_Bhi[idx] = h;
        g_Blo[idx] = __float2bfloat16_rn(v - __bfloat162float(h));
    } else {
        int j = idx - 3 * 128 * 256;                // [n=64][k=128]
        int n = j >> 7;
        int k = j & 127;
        v = W_out[k * 64 + n];
        __nv_bfloat16 h = __float2bfloat16_rn(v);
        g_Bohi[j] = h;
        g_Bolo[j] = __float2bfloat16_rn(v - __bfloat162float(h));
    }
}

// ---------------- CSR build ----------------
__global__ void hist_kernel(const int* __restrict__ ed, const int* __restrict__ rd,
                            int* __restrict__ degf, int* __restrict__ degr,
                            unsigned long long* __restrict__ status)
{
    int e = blockIdx.x * 256 + threadIdx.x;
    if (e < 2 * NB_SCAN) status[e] = 0ull;
    atomicAdd(&degf[ed[e]], 1);
    atomicAdd(&degr[rd[e]], 1);
}

__global__ void __launch_bounds__(1024)
scan_csr(const int* __restrict__ deg, int* __restrict__ rowptr,
         int* __restrict__ cursor, unsigned long long* __restrict__ status)
{
    __shared__ int sh[1024];
    __shared__ int s_excl;
    const int g = blockIdx.y;
    const int b = blockIdx.x;
    const int tid = threadIdx.x;
    const int i = b * 1024 + tid;
    const int* dg = deg + g * N_NODES;
    int* rp = rowptr + g * (N_NODES + 1);
    int* cur = cursor + g * N_NODES;
    unsigned long long* st = status + g * NB_SCAN;

    int v = (i < N_NODES) ? dg[i] : 0;
    sh[tid] = v;
    __syncthreads();
    for (int off = 1; off < 1024; off <<= 1) {
        int t = 0;
        if (tid >= off) t = sh[tid - off];
        __syncthreads();
        if (tid >= off) sh[tid] += t;
        __syncthreads();
    }
    const int bsum = sh[1023];

    if (tid == 0) {
        unsigned long long val = (unsigned long long)(unsigned)bsum;
        if (b == 0) {
            atomicExch(&st[0], FLAG_PRE | val);
            s_excl = 0;
            rp[N_NODES] = N_EDGES;
        } else {
            atomicExch(&st[b], FLAG_AGG | val);
        }
    }
    if (b > 0 && tid < 32) {
        const int lane = tid;
        long long excl = 0;
        int idx = b - 1;
        bool done = false;
        while (!done) {
            int p = idx - lane;
            unsigned long long s = 0;
            if (p >= 0) {
                do { s = atomicAdd(&st[p], 0ull); } while (!(s & (FLAG_AGG | FLAG_PRE)));
            }
            unsigned pre = __ballot_sync(0xffffffffu, (p >= 0) && (s & FLAG_PRE));
            bool inc;
            if (pre) { int k = __ffs(pre) - 1; inc = (p >= 0) && (lane <= k); done = true; }
            else     { inc = (p >= 0); if (idx < 32) done = true; }
            long long val = inc ? (long long)(s & 0xffffffffull) : 0;
#pragma unroll
            for (int o = 16; o > 0; o >>= 1) val += __shfl_down_sync(0xffffffffu, val, o);
            if (lane == 0) excl += val;
            idx -= 32;
        }
        if (lane == 0) {
            s_excl = (int)excl;
            atomicExch(&st[b], FLAG_PRE | (unsigned long long)(unsigned)(excl + bsum));
        }
    }
    __syncthreads();
    int e = s_excl + sh[tid] - v;
    if (i < N_NODES) { rp[i] = e; cur[i] = e; }
}

__global__ void fill_kernel(const int* __restrict__ es, const int* __restrict__ ed,
                            const int* __restrict__ rs, const int* __restrict__ rd,
                            int* __restrict__ curf, int* __restrict__ colf,
                            int* __restrict__ curr, int* __restrict__ colr)
{
    int e = blockIdx.x * 256 + threadIdx.x;
    int p = atomicAdd(&curf[ed[e]], 1); colf[p] = es[e];
    int q = atomicAdd(&curr[rd[e]], 1); colr[q] = rs[e];
}

// ---------------- CSR mean-aggregation: one warp per destination node ----------------
__global__ void agg_kernel(const float4* __restrict__ x,
                           const int* __restrict__ rowptr,
                           const int* __restrict__ col,
                           float4* __restrict__ out, int n)
{
    int warp = (blockIdx.x * blockDim.x + threadIdx.x) >> 5;
    int lane = threadIdx.x & 31;
    if (warp >= n) return;
    int s = rowptr[warp], e = rowptr[warp + 1];
    float4 acc = make_float4(0.f, 0.f, 0.f, 0.f);
    for (int base = s; base < e; base += 32) {
        int idx = base + lane;
        int c = (idx < e) ? col[idx] : 0;
        int m = min(32, e - base);
        for (int j = 0; j < m; j++) {
            int cc = __shfl_sync(0xffffffffu, c, j);
            float4 v = x[(size_t)cc * 32 + lane];
            acc.x += v.x; acc.y += v.y; acc.z += v.z; acc.w += v.w;
        }
    }
    float inv = 1.0f / (float)max(e - s, 1);
    acc.x *= inv; acc.y *= inv; acc.z *= inv; acc.w *= inv;
    out[(size_t)warp * 32 + lane] = acc;
}

// ---------------- 3xBF16 split-precision mma.sync GEMM ------------------------------
// C[M,BN] = [A1|A2][M,KT] @ B[BN,KT]^T + bias (+ lrelu + fused JAX dropout)
// B pre-split bf16 hi/lo, [BN][KT] row-major (k contiguous). A split on the fly.
// Per k-chunk, accumulates Ahi*Bhi + Ahi*Blo + Alo*Bhi (residual ~2^-16).
// smem per stage (bytes): Ahi[128][36bf16]=9216, Alo 9216, Bhi BN*72, Blo BN*72.

template <int KT>
__device__ __forceinline__ void ldgA(const float* __restrict__ A1,
                                     const float* __restrict__ A2,
                                     int M, int rowBase, int tid, int c, float4* pf)
{
    int kbase = c * 32;
    const float* As = (KT == 256 && kbase >= 128) ? A2 : A1;
    int kloc = kbase & 127;
    int grow = rowBase + (tid >> 1);
    int kseg = (tid & 1) * 16;
    if (grow < M) {
#pragma unroll
        for (int i = 0; i < 4; i++)
            pf[i] = *(const float4*)(As + (size_t)grow * DHID + kloc + kseg + i * 4);
    } else {
#pragma unroll
        for (int i = 0; i < 4; i++) pf[i] = make_float4(0.f, 0.f, 0.f, 0.f);
    }
}

__device__ __forceinline__ void stsA(char* stage, int tid, const float4* pf)
{
    int row = tid >> 1, kseg = (tid & 1) * 16;
#pragma unroll
    for (int i = 0; i < 4; i++) {
        float4 v = pf[i];
        __nv_bfloat16 hx = __float2bfloat16_rn(v.x), hy = __float2bfloat16_rn(v.y);
        __nv_bfloat16 hz = __float2bfloat16_rn(v.z), hw = __float2bfloat16_rn(v.w);
        __nv_bfloat16 lx = __float2bfloat16_rn(v.x - __bfloat162float(hx));
        __nv_bfloat16 ly = __float2bfloat16_rn(v.y - __bfloat162float(hy));
        __nv_bfloat16 lz = __float2bfloat16_rn(v.z - __bfloat162float(hz));
        __nv_bfloat16 lw = __float2bfloat16_rn(v.w - __bfloat162float(hw));
        int off = row * 72 + (kseg + i * 4) * 2;
        *(uint2*)(stage + off)        = make_uint2(bfp(hx, hy), bfp(hz, hw));
        *(uint2*)(stage + 9216 + off) = make_uint2(bfp(lx, ly), bfp(lz, lw));
    }
}

template <int BN, int KT>
__device__ __forceinline__ void cpB(uint32_t sbStage, int tid, int c,
                                    const __nv_bfloat16* __restrict__ Bhi,
                                    const __nv_bfloat16* __restrict__ Blo)
{
    constexpr int TPR = 256 / BN;        // threads per B row
    constexpr int BPT = 64 / TPR;        // bytes per thread (row is 64B)
    int n = tid / TPR, seg = tid % TPR;
    int kbase = c * 32;
    const char* sh = (const char*)(Bhi + n * KT + kbase) + seg * BPT;
    const char* sl = (const char*)(Blo + n * KT + kbase) + seg * BPT;
    uint32_t dh = sbStage + 18432 + n * 72 + seg * BPT;
    uint32_t dl = dh + BN * 72;
#pragma unroll
    for (int j = 0; j < BPT / 8; j++) {
        cp8(dh + j * 8, sh + j * 8);
        cp8(dl + j * 8, sl + j * 8);
    }
}

template <int BN, int KT, bool EPI>
__global__ void __launch_bounds__(256)
gemm_mma(int M,
         const float* __restrict__ A1, const float* __restrict__ A2,
         const __nv_bfloat16* __restrict__ Bhi, const __nv_bfloat16* __restrict__ Blo,
         const float* __restrict__ bias,
         uint32_t mk0, uint32_t mk1,
         float* __restrict__ C)
{
    constexpr int WN_CNT = (BN == 128) ? 4 : 2;
    constexpr int WM_CNT = 8 / WN_CNT;
    constexpr int WM = 128 / WM_CNT;     // 64 or 32
    constexpr int WN = BN / WN_CNT;      // 32
    constexpr int MT = WM / 16;          // 4 or 2
    constexpr int NT = WN / 8;           // 4
    constexpr int NC = KT / 32;
    constexpr int STAGE = 18432 + 2 * BN * 72;

    extern __shared__ char smem[];
    const uint32_t sb = smem_u32(smem);
    const int tid = threadIdx.x;
    const int wid = tid >> 5;
    const int lane = tid & 31;
    const int gid = lane >> 2;
    const int tig = lane & 3;
    const int rowBase = blockIdx.x * 128;
    const int wmBase = (wid / WN_CNT) * WM;
    const int wnBase = (wid % WN_CNT) * WN;

    float acc[MT * NT * 4];
#pragma unroll
    for (int i = 0; i < MT * NT * 4; i++) acc[i] = 0.0f;

    float4 pf[4];
    // prologue: chunk 0 into stage 0
    cpB<BN, KT>(sb, tid, 0, Bhi, Blo);
    CP_COMMIT();
    ldgA<KT>(A1, A2, M, rowBase, tid, 0, pf);
    stsA(smem, tid, pf);
    CP_WAIT0();
    __syncthreads();

    for (int c = 0; c < NC; c++) {
        const int s = c & 1;
        if (c + 1 < NC) {
            cpB<BN, KT>(sb + (s ^ 1) * STAGE, tid, c + 1, Bhi, Blo);
            CP_COMMIT();
            ldgA<KT>(A1, A2, M, rowBase, tid, c + 1, pf);
        }
        const char* st = smem + s * STAGE;
#pragma unroll
        for (int ks = 0; ks < 2; ks++) {
            const int kb = (ks * 16 + tig * 2) * 2;      // byte offset within row
            uint32_t bh[NT][2], bl[NT][2];
#pragma unroll
            for (int nt = 0; nt < NT; nt++) {
                const char* p = st + 18432 + (wnBase + nt * 8 + gid) * 72 + kb;
                bh[nt][0] = *(const uint32_t*)p;
                bh[nt][1] = *(const uint32_t*)(p + 16);
                const char* q = p + BN * 72;
                bl[nt][0] = *(const uint32_t*)q;
                bl[nt][1] = *(const uint32_t*)(q + 16);
            }
            uint32_t ah[MT][4], al[MT][4];
#pragma unroll
            for (int mt = 0; mt < MT; mt++) {
                const char* p = st + (wmBase + mt * 16 + gid) * 72 + kb;
                ah[mt][0] = *(const uint32_t*)p;
                ah[mt][1] = *(const uint32_t*)(p + 8 * 72);
                ah[mt][2] = *(const uint32_t*)(p + 16);
                ah[mt][3] = *(const uint32_t*)(p + 8 * 72 + 16);
                const char* q = p + 9216;
                al[mt][0] = *(const uint32_t*)q;
                al[mt][1] = *(const uint32_t*)(q + 8 * 72);
                al[mt][2] = *(const uint32_t*)(q + 16);
                al[mt][3] = *(const uint32_t*)(q + 8 * 72 + 16);
            }
            // pass-major order: 16 independent accumulator chains between dependents
#pragma unroll
            for (int mt = 0; mt < MT; mt++)
#pragma unroll
                for (int nt = 0; nt < NT; nt++)
                    mma_bf16(&acc[(mt * NT + nt) * 4],
                             ah[mt][0], ah[mt][1], ah[mt][2], ah[mt][3],
                             bh[nt][0], bh[nt][1]);
#pragma unroll
            for (int mt = 0; mt < MT; mt++)
#pragma unroll
                for (int nt = 0; nt < NT; nt++)
                    mma_bf16(&acc[(mt * NT + nt) * 4],
                             ah[mt][0], ah[mt][1], ah[mt][2], ah[mt][3],
                             bl[nt][0], bl[nt][1]);
#pragma unroll
            for (int mt = 0; mt < MT; mt++)
#pragma unroll
                for (int nt = 0; nt < NT; nt++)
                    mma_bf16(&acc[(mt * NT + nt) * 4],
                             al[mt][0], al[mt][1], al[mt][2], al[mt][3],
                             bh[nt][0], bh[nt][1]);
        }
        if (c + 1 < NC) {
            stsA(smem + (s ^ 1) * STAGE, tid, pf);
            CP_WAIT0();
            __syncthreads();
        }
    }

    // epilogue: bias (+ leaky_relu + inline exact-JAX dropout)
#pragma unroll
    for (int mt = 0; mt < MT; mt++) {
        int r0 = rowBase + wmBase + mt * 16 + gid;
#pragma unroll
        for (int nt = 0; nt < NT; nt++) {
            const float* cf = &acc[(mt * NT + nt) * 4];
            int c0 = wnBase + nt * 8 + tig * 2;
            float b0 = __ldg(&bias[c0]), b1 = __ldg(&bias[c0 + 1]);
#pragma unroll
            for (int h = 0; h < 2; h++) {
                int rr = r0 + h * 8;
                if (rr < M) {
                    float o0 = cf[2 * h] + b0;
                    float o1 = cf[2 * h + 1] + b1;
                    if (EPI) {
                        o0 = (o0 >= 0.0f) ? o0 : 0.01f * o0;
                        o1 = (o1 >= 0.0f) ? o1 : 0.01f * o1;
                        uint32_t fl = (uint32_t)rr * 128u + (uint32_t)c0;
                        o0 = drop_keep(mk0, mk1, fl)      ? o0 * (1.0f / 0.9f) : 0.0f;
                        o1 = drop_keep(mk0, mk1, fl + 1u) ? o1 * (1.0f / 0.9f) : 0.0f;
                    }
                    *(float2*)(C + (size_t)rr * BN + c0) = make_float2(o0, o1);
                }
            }
        }
    }
}

// ---------------- host orchestration ----------------
extern "C" void kernel_launch(void* const* d_in, const int* in_sizes, int n_in,
                              void* d_out, int out_size)
{
    const float* x_src  = (const float*)d_in[0];
    const float* x_tgt  = (const float*)d_in[1];
    const float* Wl_tgt = (const float*)d_in[2];
    const float* bl_tgt = (const float*)d_in[3];
    const float* Wr_tgt = (const float*)d_in[4];
    const float* Wl_src = (const float*)d_in[5];
    const float* bl_src = (const float*)d_in[6];
    const float* Wr_src = (const float*)d_in[7];
    const float* W_out  = (const float*)d_in[8];
    const float* b_out  = (const float*)d_in[9];
    const int* edge_src = (const int*)d_in[10];
    const int* edge_dst = (const int*)d_in[11];
    const int* rev_src  = (const int*)d_in[12];
    const int* rev_dst  = (const int*)d_in[13];
    float* out = (float*)d_out;

    float *agg, *xt1, *xs1, *xs2;
    __nv_bfloat16 *Bhi, *Blo, *Bohi, *Bolo;
    int *deg, *rp, *cur, *col;
    unsigned long long* status;
    cudaGetSymbolAddress((void**)&agg,    g_agg);
    cudaGetSymbolAddress((void**)&xt1,    g_xt1);
    cudaGetSymbolAddress((void**)&xs1,    g_xs1);
    cudaGetSymbolAddress((void**)&xs2,    g_xs2);
    cudaGetSymbolAddress((void**)&deg,    g_deg);
    cudaGetSymbolAddress((void**)&rp,     g_rp);
    cudaGetSymbolAddress((void**)&cur,    g_cur);
    cudaGetSymbolAddress((void**)&col,    g_col);
    cudaGetSymbolAddress((void**)&status, g_status);
    cudaGetSymbolAddress((void**)&Bhi,    g_Bhi);
    cudaGetSymbolAddress((void**)&Blo,    g_Blo);
    cudaGetSymbolAddress((void**)&Bohi,   g_Bohi);
    cudaGetSymbolAddress((void**)&Bolo,   g_Bolo);

    int* degf = deg;
    int* degr = deg + N_NODES;
    int* rpf  = rp;
    int* rpr  = rp + (N_NODES + 1);
    int* curf = cur;
    int* curr = cur + N_NODES;
    int* colf = col;
    int* colr = col + N_EDGES;

    uint32_t k0a, k1a, k0b, k1b, k0c, k1c;
    threefry2x32(0u, 42u, 0u, 0u, k0a, k1a);  // layer0 target  (fold 0)
    threefry2x32(0u, 42u, 0u, 1u, k0b, k1b);  // layer0 source  (fold 1)
    threefry2x32(0u, 42u, 0u, 3u, k0c, k1c);  // layer1 source  (fold 3)

    const int EB = N_EDGES / 256;
    const int AGGB = N_NODES / 8;
    const int GB = (N_NODES + 127) / 128;                  // 782
    const int SM128 = 2 * (18432 + 2 * 128 * 72);          // 73728
    const int SM64  = 2 * (18432 + 2 * 64 * 72);           // 55296

    cudaFuncSetAttribute(gemm_mma<128, 256, true>,
                         cudaFuncAttributeMaxDynamicSharedMemorySize, SM128);
    cudaFuncSetAttribute(gemm_mma<64, 128, false>,
                         cudaFuncAttributeMaxDynamicSharedMemorySize, SM64);

    // ncu launch idx (memsets not counted): prep0, hist1, scan2, fill3, agg4, gemm5
    prep_w<<<416, 256>>>(Wl_tgt, Wr_tgt, Wl_src, Wr_src, W_out);
    cudaMemsetAsync(deg, 0, 2 * N_NODES * sizeof(int));
    hist_kernel<<<EB, 256>>>(edge_dst, rev_dst, degf, degr, status);
    scan_csr<<<dim3(NB_SCAN, 2), 1024>>>(deg, rp, cur, status);
    fill_kernel<<<EB, 256>>>(edge_src, edge_dst, rev_src, rev_dst, curf, colf, curr, colr);

    // layer 0, target conv
    agg_kernel<<<AGGB, 256>>>((const float4*)x_src, rpf, colf, (float4*)agg, N_NODES);
    gemm_mma<128, 256, true><<<GB, 256, SM128>>>(N_NODES, agg, x_tgt,
        Bhi + 0 * 32768, Blo + 0 * 32768, bl_tgt, k0a, k1a, xt1);

    // layer 0, source conv
    agg_kernel<<<AGGB, 256>>>((const float4*)x_tgt, rpr, colr, (float4*)agg, N_NODES);
    gemm_mma<128, 256, true><<<GB, 256, SM128>>>(N_NODES, agg, x_src,
        Bhi + 1 * 32768, Blo + 1 * 32768, bl_src, k0b, k1b, xs1);

    // layer 1, source conv only (layer-1 target embedding is dead code)
    agg_kernel<<<AGGB, 256>>>((const float4*)xt1, rpr, colr, (float4*)agg, N_NODES);
    gemm_mma<128, 256, true><<<GB, 256, SM128>>>(N_NODES, agg, xs1,
        Bhi + 2 * 32768, Blo + 2 * 32768, bl_src + DHID, k0c, k1c, xs2);

    // output projection
    gemm_mma<64, 128, false><<<GB, 256, SM64>>>(N_NODES, xs2, nullptr,
        Bohi, Bolo, b_out, 0u, 0u, out);
}

// round 16
// speedup vs baseline: 1.4332x; 1.0911x over previous
#include <cuda_runtime.h>
#include <cuda_bf16.h>
#include <cstdint>

// ---------------- problem constants ----------------
#define N_NODES   100000
#define N_EDGES   1600000
#define DHID      128
#define OUTD      64
#define NB_SCAN   98              // ceil(N_NODES/1024)
#define FLAG_AGG  (1ull << 62)
#define FLAG_PRE  (1ull << 63)

// ---------------- persistent device scratch (no cudaMalloc allowed) ----------------
__device__ float g_agg[N_NODES * DHID];
__device__ float g_xt1[N_NODES * DHID];
__device__ float g_xs1[N_NODES * DHID];
__device__ float g_xs2[N_NODES * DHID];
__device__ int g_deg[2 * N_NODES];
__device__ int g_rp[2 * (N_NODES + 1)];
__device__ int g_cur[2 * N_NODES];
__device__ int g_col[2 * N_EDGES];
__device__ unsigned long long g_status[2 * NB_SCAN];
// pre-transposed + bf16-split weights: [conv][n=128][k=256] and out [n=64][k=128]
__device__ __nv_bfloat16 g_Bhi[3 * 128 * 256];
__device__ __nv_bfloat16 g_Blo[3 * 128 * 256];
__device__ __nv_bfloat16 g_Bohi[64 * 128];
__device__ __nv_bfloat16 g_Bolo[64 * 128];

// ---------------- Threefry-2x32 (20 rounds), matches JAX exactly ----------------
__host__ __device__ __forceinline__ void threefry2x32(uint32_t k0, uint32_t k1,
                                                      uint32_t x0, uint32_t x1,
                                                      uint32_t& o0, uint32_t& o1)
{
    uint32_t k2 = k0 ^ k1 ^ 0x1BD11BDAu;
    x0 += k0; x1 += k1;
#define TF_R(r) { x0 += x1; x1 = (x1 << (r)) | (x1 >> (32 - (r))); x1 ^= x0; }
    TF_R(13) TF_R(15) TF_R(26) TF_R(6)  x0 += k1; x1 += k2 + 1u;
    TF_R(17) TF_R(29) TF_R(16) TF_R(24) x0 += k2; x1 += k0 + 2u;
    TF_R(13) TF_R(15) TF_R(26) TF_R(6)  x0 += k0; x1 += k1 + 3u;
    TF_R(17) TF_R(29) TF_R(16) TF_R(24) x0 += k1; x1 += k2 + 4u;
    TF_R(13) TF_R(15) TF_R(26) TF_R(6)  x0 += k2; x1 += k0 + 5u;
#undef TF_R
    o0 = x0; o1 = x1;
}

// partitionable-threefry keep bit (x32 float path) — verified exact vs reference
__device__ __forceinline__ bool drop_keep(uint32_t k0, uint32_t k1, uint32_t flat)
{
    uint32_t o0, o1;
    threefry2x32(k0, k1, 0u, flat, o0, o1);
    uint32_t bits = o0 ^ o1;
    float u = __uint_as_float((bits >> 9) | 0x3f800000u) - 1.0f;
    return u < 0.9f;
}

// ---------------- small helpers ----------------
__device__ __forceinline__ uint32_t smem_u32(const void* p)
{
    uint32_t a;
    asm("{ .reg .u64 t; cvta.to.shared.u64 t, %1; cvt.u32.u64 %0, t; }" : "=r"(a) : "l"(p));
    return a;
}
__device__ __forceinline__ void cp8(uint32_t dst, const void* src)
{
    asm volatile("cp.async.ca.shared.global [%0], [%1], 8;" :: "r"(dst), "l"(src));
}
#define CP_COMMIT() asm volatile("cp.async.commit_group;" ::: "memory")
#define CP_WAIT0()  asm volatile("cp.async.wait_group 0;" ::: "memory")
#define LDMX4(r0, r1, r2, r3, a) \
    asm volatile("ldmatrix.sync.aligned.m8n8.x4.shared.b16 {%0,%1,%2,%3}, [%4];" \
                 : "=r"(r0), "=r"(r1), "=r"(r2), "=r"(r3) : "r"(a))

__device__ __forceinline__ uint32_t bfp(__nv_bfloat16 a, __nv_bfloat16 b)
{
    uint16_t ra = *reinterpret_cast<uint16_t*>(&a);
    uint16_t rb = *reinterpret_cast<uint16_t*>(&b);
    return (uint32_t)ra | ((uint32_t)rb << 16);
}
__device__ __forceinline__ void mma_bf16(float* c,
                                         uint32_t a0, uint32_t a1, uint32_t a2, uint32_t a3,
                                         uint32_t b0, uint32_t b1)
{
    asm volatile("mma.sync.aligned.m16n8k16.row.col.f32.bf16.bf16.f32 "
                 "{%0,%1,%2,%3}, {%4,%5,%6,%7}, {%8,%9}, {%0,%1,%2,%3};"
                 : "+f"(c[0]), "+f"(c[1]), "+f"(c[2]), "+f"(c[3])
                 : "r"(a0), "r"(a1), "r"(a2), "r"(a3), "r"(b0), "r"(b1));
}

// ---------------- hist + fused weight prep ----------------
// blocks [0, 6250): edge histogram; blocks [6250, 6666): weight transpose+split
__global__ void hist_prep(const int* __restrict__ ed, const int* __restrict__ rd,
                          int* __restrict__ degf, int* __restrict__ degr,
                          const float* __restrict__ Wl_tgt, const float* __restrict__ Wr_tgt,
                          const float* __restrict__ Wl_src, const float* __restrict__ Wr_src,
                          const float* __restrict__ W_out)
{
    if (blockIdx.x < 6250) {
        int e = blockIdx.x * 256 + threadIdx.x;
        atomicAdd(&degf[ed[e]], 1);
        atomicAdd(&degr[rd[e]], 1);
    } else {
        int idx = (blockIdx.x - 6250) * 256 + threadIdx.x;   // covers 106496 exactly
        float v;
        if (idx < 3 * 128 * 256) {
            int c = idx >> 15;
            int rem = idx & 32767;
            int n = rem >> 8;
            int k = rem & 255;
            const float* Wl = (c == 0) ? Wl_tgt : (c == 1 ? Wl_src : Wl_src + 16384);
            const float* Wr = (c == 0) ? Wr_tgt : (c == 1 ? Wr_src : Wr_src + 16384);
            v = (k < 128) ? Wl[k * 128 + n] : Wr[(k - 128) * 128 + n];
            __nv_bfloat16 h = __float2bfloat16_rn(v);
            g_Bhi[idx] = h;
            g_Blo[idx] = __float2bfloat16_rn(v - __bfloat162float(h));
        } else {
            int j = idx - 3 * 128 * 256;
            int n = j >> 7;
            int k = j & 127;
            v = W_out[k * 64 + n];
            __nv_bfloat16 h = __float2bfloat16_rn(v);
            g_Bohi[j] = h;
            g_Bolo[j] = __float2bfloat16_rn(v - __bfloat162float(h));
        }
    }
}

// ---------------- single-pass exclusive scan: decoupled lookback, both graphs --------
__global__ void __launch_bounds__(1024)
scan_csr(const int* __restrict__ deg, int* __restrict__ rowptr,
         int* __restrict__ cursor, unsigned long long* __restrict__ status)
{
    __shared__ int sh[1024];
    __shared__ int s_excl;
    const int g = blockIdx.y;
    const int b = blockIdx.x;
    const int tid = threadIdx.x;
    const int i = b * 1024 + tid;
    const int* dg = deg + g * N_NODES;
    int* rp = rowptr + g * (N_NODES + 1);
    int* cur = cursor + g * N_NODES;
    unsigned long long* st = status + g * NB_SCAN;

    int v = (i < N_NODES) ? dg[i] : 0;
    sh[tid] = v;
    __syncthreads();
    for (int off = 1; off < 1024; off <<= 1) {
        int t = 0;
        if (tid >= off) t = sh[tid - off];
        __syncthreads();
        if (tid >= off) sh[tid] += t;
        __syncthreads();
    }
    const int bsum = sh[1023];

    if (tid == 0) {
        unsigned long long val = (unsigned long long)(unsigned)bsum;
        if (b == 0) {
            atomicExch(&st[0], FLAG_PRE | val);
            s_excl = 0;
            rp[N_NODES] = N_EDGES;
        } else {
            atomicExch(&st[b], FLAG_AGG | val);
        }
    }
    if (b > 0 && tid < 32) {
        const int lane = tid;
        long long excl = 0;
        int idx = b - 1;
        bool done = false;
        while (!done) {
            int p = idx - lane;
            unsigned long long s = 0;
            if (p >= 0) {
                do { s = atomicAdd(&st[p], 0ull); } while (!(s & (FLAG_AGG | FLAG_PRE)));
            }
            unsigned pre = __ballot_sync(0xffffffffu, (p >= 0) && (s & FLAG_PRE));
            bool inc;
            if (pre) { int k = __ffs(pre) - 1; inc = (p >= 0) && (lane <= k); done = true; }
            else     { inc = (p >= 0); if (idx < 32) done = true; }
            long long val = inc ? (long long)(s & 0xffffffffull) : 0;
#pragma unroll
            for (int o = 16; o > 0; o >>= 1) val += __shfl_down_sync(0xffffffffu, val, o);
            if (lane == 0) excl += val;
            idx -= 32;
        }
        if (lane == 0) {
            s_excl = (int)excl;
            atomicExch(&st[b], FLAG_PRE | (unsigned long long)(unsigned)(excl + bsum));
        }
    }
    __syncthreads();
    int e = s_excl + sh[tid] - v;
    if (i < N_NODES) { rp[i] = e; cur[i] = e; }
}

// fill also re-zeroes deg + status for the next graph replay (they are fully
// consumed by scan_csr, which ran before this launch; globals start zeroed).
__global__ void fill_kernel(const int* __restrict__ es, const int* __restrict__ ed,
                            const int* __restrict__ rs, const int* __restrict__ rd,
                            int* __restrict__ curf, int* __restrict__ colf,
                            int* __restrict__ curr, int* __restrict__ colr,
                            int* __restrict__ deg, unsigned long long* __restrict__ status)
{
    int e = blockIdx.x * 256 + threadIdx.x;
    if (e < 2 * N_NODES) deg[e] = 0;
    if (e < 2 * NB_SCAN) status[e] = 0ull;
    int p = atomicAdd(&curf[ed[e]], 1); colf[p] = es[e];
    int q = atomicAdd(&curr[rd[e]], 1); colr[q] = rs[e];
}

// ---------------- CSR mean-aggregation: one warp per destination node ----------------
__global__ void agg_kernel(const float4* __restrict__ x,
                           const int* __restrict__ rowptr,
                           const int* __restrict__ col,
                           float4* __restrict__ out, int n)
{
    int warp = (blockIdx.x * blockDim.x + threadIdx.x) >> 5;
    int lane = threadIdx.x & 31;
    if (warp >= n) return;
    int s = rowptr[warp], e = rowptr[warp + 1];
    float4 acc = make_float4(0.f, 0.f, 0.f, 0.f);
    for (int base = s; base < e; base += 32) {
        int idx = base + lane;
        int c = (idx < e) ? col[idx] : 0;
        int m = min(32, e - base);
        for (int j = 0; j < m; j++) {
            int cc = __shfl_sync(0xffffffffu, c, j);
            float4 v = x[(size_t)cc * 32 + lane];
            acc.x += v.x; acc.y += v.y; acc.z += v.z; acc.w += v.w;
        }
    }
    float inv = 1.0f / (float)max(e - s, 1);
    acc.x *= inv; acc.y *= inv; acc.z *= inv; acc.w *= inv;
    out[(size_t)warp * 32 + lane] = acc;
}

// ---------------- 3xBF16 split-precision mma.sync GEMM with ldmatrix ----------------
// C[M,BN] = [A1|A2][M,KT] @ B[BN,KT]^T + bias (+ lrelu + fused JAX dropout)
// smem stage layout (stride 80 B/row -> conflict-free ldmatrix):
//   A_hi[128][80B]=10240, A_lo +10240, B_hi at 20480 (BN*80), B_lo after it.
#define ROWB 80

template <int KT>
__device__ __forceinline__ void ldgA(const float* __restrict__ A1,
                                     const float* __restrict__ A2,
                                     int M, int rowBase, int tid, int c, float4* pf)
{
    int kbase = c * 32;
    const float* As = (KT == 256 && kbase >= 128) ? A2 : A1;
    int kloc = kbase & 127;
    int grow = rowBase + (tid >> 1);
    int kseg = (tid & 1) * 16;
    if (grow < M) {
#pragma unroll
        for (int i = 0; i < 4; i++)
            pf[i] = *(const float4*)(As + (size_t)grow * DHID + kloc + kseg + i * 4);
    } else {
#pragma unroll
        for (int i = 0; i < 4; i++) pf[i] = make_float4(0.f, 0.f, 0.f, 0.f);
    }
}

__device__ __forceinline__ void stsA(char* stage, int tid, const float4* pf)
{
    int row = tid >> 1, kseg = (tid & 1) * 16;
#pragma unroll
    for (int i = 0; i < 4; i++) {
        float4 v = pf[i];
        __nv_bfloat16 hx = __float2bfloat16_rn(v.x), hy = __float2bfloat16_rn(v.y);
        __nv_bfloat16 hz = __float2bfloat16_rn(v.z), hw = __float2bfloat16_rn(v.w);
        __nv_bfloat16 lx = __float2bfloat16_rn(v.x - __bfloat162float(hx));
        __nv_bfloat16 ly = __float2bfloat16_rn(v.y - __bfloat162float(hy));
        __nv_bfloat16 lz = __float2bfloat16_rn(v.z - __bfloat162float(hz));
        __nv_bfloat16 lw = __float2bfloat16_rn(v.w - __bfloat162float(hw));
        int off = row * ROWB + (kseg + i * 4) * 2;
        *(uint2*)(stage + off)         = make_uint2(bfp(hx, hy), bfp(hz, hw));
        *(uint2*)(stage + 10240 + off) = make_uint2(bfp(lx, ly), bfp(lz, lw));
    }
}

template <int BN, int KT>
__device__ __forceinline__ void cpB(uint32_t sbStage, int tid, int c,
                                    const __nv_bfloat16* __restrict__ Bhi,
                                    const __nv_bfloat16* __restrict__ Blo)
{
    constexpr int TPR = 256 / BN;        // threads per B row
    constexpr int BPT = 64 / TPR;        // bytes per thread (row data is 64B)
    int n = tid / TPR, seg = tid % TPR;
    int kbase = c * 32;
    const char* sh = (const char*)(Bhi + n * KT + kbase) + seg * BPT;
    const char* sl = (const char*)(Blo + n * KT + kbase) + seg * BPT;
    uint32_t dh = sbStage + 20480 + n * ROWB + seg * BPT;
    uint32_t dl = dh + BN * ROWB;
#pragma unroll
    for (int j = 0; j < BPT / 8; j++) {
        cp8(dh + j * 8, sh + j * 8);
        cp8(dl + j * 8, sl + j * 8);
    }
}

template <int BN, int KT, bool EPI>
__global__ void __launch_bounds__(256)
gemm_mma(int M,
         const float* __restrict__ A1, const float* __restrict__ A2,
         const __nv_bfloat16* __restrict__ Bhi, const __nv_bfloat16* __restrict__ Blo,
         const float* __restrict__ bias,
         uint32_t mk0, uint32_t mk1,
         float* __restrict__ C)
{
    constexpr int WN_CNT = (BN == 128) ? 4 : 2;
    constexpr int WM = 128 / (8 / WN_CNT);   // 64 or 32
    constexpr int WN = BN / WN_CNT;          // 32
    constexpr int MT = WM / 16;              // 4 or 2
    constexpr int NT = WN / 8;               // 4
    constexpr int NC = KT / 32;
    constexpr int STAGE = 20480 + 2 * BN * ROWB;

    extern __shared__ char smem[];
    const uint32_t sb = smem_u32(smem);
    const int tid = threadIdx.x;
    const int wid = tid >> 5;
    const int lane = tid & 31;
    const int gid = lane >> 2;
    const int tig = lane & 3;
    const int rowBase = blockIdx.x * 128;
    const int wmBase = (wid / WN_CNT) * WM;
    const int wnBase = (wid % WN_CNT) * WN;

    // per-lane ldmatrix address components (byte offsets within a stage)
    const int aRow = wmBase + (lane & 7) + (lane & 8);       // + mt*16
    const int aKh  = (lane & 16) ? 16 : 0;                   // k-half byte offset
    const int bRow = wnBase + (lane & 7) + ((lane & 16) ? 8 : 0);  // + pair*16
    const int bKh  = (lane & 8) ? 16 : 0;

    float acc[MT * NT * 4];
#pragma unroll
    for (int i = 0; i < MT * NT * 4; i++) acc[i] = 0.0f;

    float4 pf[4];
    // prologue: chunk 0 into stage 0
    cpB<BN, KT>(sb, tid, 0, Bhi, Blo);
    CP_COMMIT();
    ldgA<KT>(A1, A2, M, rowBase, tid, 0, pf);
    stsA(smem, tid, pf);
    CP_WAIT0();
    __syncthreads();

    for (int c = 0; c < NC; c++) {
        const int s = c & 1;
        if (c + 1 < NC) {
            cpB<BN, KT>(sb + (s ^ 1) * STAGE, tid, c + 1, Bhi, Blo);
            CP_COMMIT();
            ldgA<KT>(A1, A2, M, rowBase, tid, c + 1, pf);
        }
        const uint32_t stA = sb + s * STAGE;
        const uint32_t stB = stA + 20480;
#pragma unroll
        for (int ks = 0; ks < 2; ks++) {
            const int ko = ks * 32;                          // k byte offset
            uint32_t ah[MT][4], al[MT][4], bh[NT][2], bl[NT][2];
#pragma unroll
            for (int p = 0; p < NT / 2; p++) {
                uint32_t ad = stB + (bRow + p * 16) * ROWB + ko + bKh;
                LDMX4(bh[2 * p][0], bh[2 * p][1], bh[2 * p + 1][0], bh[2 * p + 1][1], ad);
                LDMX4(bl[2 * p][0], bl[2 * p][1], bl[2 * p + 1][0], bl[2 * p + 1][1],
                      ad + BN * ROWB);
            }
#pragma unroll
            for (int mt = 0; mt < MT; mt++) {
                uint32_t ad = stA + (aRow + mt * 16) * ROWB + ko + aKh;
                LDMX4(ah[mt][0], ah[mt][1], ah[mt][2], ah[mt][3], ad);
                LDMX4(al[mt][0], al[mt][1], al[mt][2], al[mt][3], ad + 10240);
            }
#pragma unroll
            for (int mt = 0; mt < MT; mt++)
#pragma unroll
                for (int nt = 0; nt < NT; nt++)
                    mma_bf16(&acc[(mt * NT + nt) * 4],
                             ah[mt][0], ah[mt][1], ah[mt][2], ah[mt][3],
                             bh[nt][0], bh[nt][1]);
#pragma unroll
            for (int mt = 0; mt < MT; mt++)
#pragma unroll
                for (int nt = 0; nt < NT; nt++)
                    mma_bf16(&acc[(mt * NT + nt) * 4],
                             ah[mt][0], ah[mt][1], ah[mt][2], ah[mt][3],
                             bl[nt][0], bl[nt][1]);
#pragma unroll
            for (int mt = 0; mt < MT; mt++)
#pragma unroll
                for (int nt = 0; nt < NT; nt++)
                    mma_bf16(&acc[(mt * NT + nt) * 4],
                             al[mt][0], al[mt][1], al[mt][2], al[mt][3],
                             bh[nt][0], bh[nt][1]);
        }
        if (c + 1 < NC) {
            stsA(smem + (s ^ 1) * STAGE, tid, pf);
            CP_WAIT0();
            __syncthreads();
        }
    }

    // epilogue: bias (+ leaky_relu + inline exact-JAX dropout)
#pragma unroll
    for (int mt = 0; mt < MT; mt++) {
        int r0 = rowBase + wmBase + mt * 16 + gid;
#pragma unroll
        for (int nt = 0; nt < NT; nt++) {
            const float* cf = &acc[(mt * NT + nt) * 4];
            int c0 = wnBase + nt * 8 + tig * 2;
            float b0 = __ldg(&bias[c0]), b1 = __ldg(&bias[c0 + 1]);
#pragma unroll
            for (int h = 0; h < 2; h++) {
                int rr = r0 + h * 8;
                if (rr < M) {
                    float o0 = cf[2 * h] + b0;
                    float o1 = cf[2 * h + 1] + b1;
                    if (EPI) {
                        o0 = (o0 >= 0.0f) ? o0 : 0.01f * o0;
                        o1 = (o1 >= 0.0f) ? o1 : 0.01f * o1;
                        uint32_t fl = (uint32_t)rr * 128u + (uint32_t)c0;
                        o0 = drop_keep(mk0, mk1, fl)      ? o0 * (1.0f / 0.9f) : 0.0f;
                        o1 = drop_keep(mk0, mk1, fl + 1u) ? o1 * (1.0f / 0.9f) : 0.0f;
                    }
                    *(float2*)(C + (size_t)rr * BN + c0) = make_float2(o0, o1);
                }
            }
        }
    }
}

// ---------------- host orchestration ----------------
extern "C" void kernel_launch(void* const* d_in, const int* in_sizes, int n_in,
                              void* d_out, int out_size)
{
    const float* x_src  = (const float*)d_in[0];
    const float* x_tgt  = (const float*)d_in[1];
    const float* Wl_tgt = (const float*)d_in[2];
    const float* bl_tgt = (const float*)d_in[3];
    const float* Wr_tgt = (const float*)d_in[4];
    const float* Wl_src = (const float*)d_in[5];
    const float* bl_src = (const float*)d_in[6];
    const float* Wr_src = (const float*)d_in[7];
    const float* W_out  = (const float*)d_in[8];
    const float* b_out  = (const float*)d_in[9];
    const int* edge_src = (const int*)d_in[10];
    const int* edge_dst = (const int*)d_in[11];
    const int* rev_src  = (const int*)d_in[12];
    const int* rev_dst  = (const int*)d_in[13];
    float* out = (float*)d_out;

    float *agg, *xt1, *xs1, *xs2;
    __nv_bfloat16 *Bhi, *Blo, *Bohi, *Bolo;
    int *deg, *rp, *cur, *col;
    unsigned long long* status;
    cudaGetSymbolAddress((void**)&agg,    g_agg);
    cudaGetSymbolAddress((void**)&xt1,    g_xt1);
    cudaGetSymbolAddress((void**)&xs1,    g_xs1);
    cudaGetSymbolAddress((void**)&xs2,    g_xs2);
    cudaGetSymbolAddress((void**)&deg,    g_deg);
    cudaGetSymbolAddress((void**)&rp,     g_rp);
    cudaGetSymbolAddress((void**)&cur,    g_cur);
    cudaGetSymbolAddress((void**)&col,    g_col);
    cudaGetSymbolAddress((void**)&status, g_status);
    cudaGetSymbolAddress((void**)&Bhi,    g_Bhi);
    cudaGetSymbolAddress((void**)&Blo,    g_Blo);
    cudaGetSymbolAddress((void**)&Bohi,   g_Bohi);
    cudaGetSymbolAddress((void**)&Bolo,   g_Bolo);

    int* degf = deg;
    int* degr = deg + N_NODES;
    int* rpf  = rp;
    int* rpr  = rp + (N_NODES + 1);
    int* curf = cur;
    int* curr = cur + N_NODES;
    int* colf = col;
    int* colr = col + N_EDGES;

    uint32_t k0a, k1a, k0b, k1b, k0c, k1c;
    threefry2x32(0u, 42u, 0u, 0u, k0a, k1a);  // layer0 target  (fold 0)
    threefry2x32(0u, 42u, 0u, 1u, k0b, k1b);  // layer0 source  (fold 1)
    threefry2x32(0u, 42u, 0u, 3u, k0c, k1c);  // layer1 source  (fold 3)

    const int EB = N_EDGES / 256;
    const int AGGB = N_NODES / 8;
    const int GB = (N_NODES + 127) / 128;                  // 782
    const int SM128 = 2 * (20480 + 2 * 128 * ROWB);        // 81920
    const int SM64  = 2 * (20480 + 2 * 64 * ROWB);         // 61440

    cudaFuncSetAttribute(gemm_mma<128, 256, true>,
                         cudaFuncAttributeMaxDynamicSharedMemorySize, SM128);
    cudaFuncSetAttribute(gemm_mma<64, 128, false>,
                         cudaFuncAttributeMaxDynamicSharedMemorySize, SM64);

    // launch stream (no memsets): hist+prep(0), scan(1), fill(2), agg1(3), gemm1(4)
    hist_prep<<<EB + 416, 256>>>(edge_dst, rev_dst, degf, degr,
                                 Wl_tgt, Wr_tgt, Wl_src, Wr_src, W_out);
    scan_csr<<<dim3(NB_SCAN, 2), 1024>>>(deg, rp, cur, status);
    fill_kernel<<<EB, 256>>>(edge_src, edge_dst, rev_src, rev_dst,
                             curf, colf, curr, colr, deg, status);

    // layer 0, target conv
    agg_kernel<<<AGGB, 256>>>((const float4*)x_src, rpf, colf, (float4*)agg, N_NODES);
    gemm_mma<128, 256, true><<<GB, 256, SM128>>>(N_NODES, agg, x_tgt,
        Bhi + 0 * 32768, Blo + 0 * 32768, bl_tgt, k0a, k1a, xt1);

    // layer 0, source conv
    agg_kernel<<<AGGB, 256>>>((const float4*)x_tgt, rpr, colr, (float4*)agg, N_NODES);
    gemm_mma<128, 256, true><<<GB, 256, SM128>>>(N_NODES, agg, x_src,
        Bhi + 1 * 32768, Blo + 1 * 32768, bl_src, k0b, k1b, xs1);

    // layer 1, source conv only (layer-1 target embedding is dead code)
    agg_kernel<<<AGGB, 256>>>((const float4*)xt1, rpr, colr, (float4*)agg, N_NODES);
    gemm_mma<128, 256, true><<<GB, 256, SM128>>>(N_NODES, agg, xs1,
        Bhi + 2 * 32768, Blo + 2 * 32768, bl_src + DHID, k0c, k1c, xs2);

    // output projection
    gemm_mma<64, 128, false><<<GB, 256, SM64>>>(N_NODES, xs2, nullptr,
        Bohi, Bolo, b_out, 0u, 0u, out);
}